// round 7
// baseline (speedup 1.0000x reference)
#include <cuda_runtime.h>
#include <cstdint>

#define B_   4
#define N_   2048
#define DIM_ 1024
#define H_   16
#define HD_  64
#define E3_  3072
#define M_   8192
#define SCALE_ 0.125f

// Scratch q/k/v in [B,H,N,HD], values tf32-RN-rounded at GEMM epilogue
__device__ float g_q[(size_t)B_ * H_ * N_ * HD_];
__device__ float g_k[(size_t)B_ * H_ * N_ * HD_];
__device__ float g_v[(size_t)B_ * H_ * N_ * HD_];

// ---------------------------------------------------------------------------
// helpers
// ---------------------------------------------------------------------------
__device__ __forceinline__ float tf32r(float x) {
    uint32_t u;
    asm("cvt.rna.tf32.f32 %0, %1;" : "=r"(u) : "f"(x));
    return __uint_as_float(u);
}
__device__ __forceinline__ uint32_t tf32u(float x) {   // round + reinterpret
    uint32_t u;
    asm("cvt.rna.tf32.f32 %0, %1;" : "=r"(u) : "f"(x));
    return u;
}
__device__ __forceinline__ uint32_t smem_u32(const void* p) {
    uint32_t a;
    asm("{ .reg .u64 t; cvta.to.shared.u64 t, %1; cvt.u32.u64 %0, t; }"
        : "=r"(a) : "l"(p));
    return a;
}
__device__ __forceinline__ void cpasync16(uint32_t dst, const void* src) {
    asm volatile("cp.async.cg.shared.global [%0], [%1], 16;"
                 :: "r"(dst), "l"(src) : "memory");
}
// d += a(16x8) * b(8x8) ; tf32 in, f32 accum
__device__ __forceinline__ void mma8(float* d,
                                     uint32_t a0, uint32_t a1, uint32_t a2, uint32_t a3,
                                     uint32_t b0, uint32_t b1) {
    asm volatile(
        "mma.sync.aligned.m16n8k8.row.col.f32.tf32.tf32.f32 "
        "{%0,%1,%2,%3}, {%4,%5,%6,%7}, {%8,%9}, {%0,%1,%2,%3};"
        : "+f"(d[0]), "+f"(d[1]), "+f"(d[2]), "+f"(d[3])
        : "r"(a0), "r"(a1), "r"(a2), "r"(a3), "r"(b0), "r"(b1));
}
__device__ __forceinline__ uint32_t f2u(float x) { return __float_as_uint(x); }

// ---------------------------------------------------------------------------
// Kernel 1: QKV projection, mma.sync tf32, rounding fused into fragment loads.
// C[m][e] = sum_d X[m][d]*W[e][d] + bias[e] -> scatter g_q/g_k/g_v (rounded)
// CTA 128x128, BK=32 double-buffered, 256 thr, 8 warps (2m x 4n), tile 64x32.
// (Same resource shape as the R4-passing kernel: 64 accum regs/thread.)
// ---------------------------------------------------------------------------
#define GSTR 36
#define G_TILE (128 * GSTR)
#define G_SMEM_BYTES (4 * G_TILE * 4)

__global__ __launch_bounds__(256) void qkv_mma_kernel(
    const float* __restrict__ X, const float* __restrict__ W,
    const float* __restrict__ bias)
{
    extern __shared__ float smg[];
    float* As[2] = { smg,              smg + G_TILE };
    float* Bs[2] = { smg + 2 * G_TILE, smg + 3 * G_TILE };
    const uint32_t sbase = smem_u32(smg);

    const int tid  = threadIdx.x;
    const int wid  = tid >> 5;
    const int lane = tid & 31;
    const int g    = lane >> 2;
    const int t    = lane & 3;
    const int warpM = (wid >> 2) * 64;
    const int warpN = (wid & 3) * 32;
    const int mBase = blockIdx.y * 128;
    const int eBase = blockIdx.x * 128;

    const int lrow  = tid >> 1;       // 0..127
    const int lhalf = tid & 1;        // 16-float halves

    auto load_stage = [&](int buf, int s) {
        const int k0 = s * 32;
        const float* ax = X + (size_t)(mBase + lrow) * DIM_ + k0 + lhalf * 16;
        const float* bx = W + (size_t)(eBase + lrow) * DIM_ + k0 + lhalf * 16;
        uint32_t da = sbase + (uint32_t)(((buf ? G_TILE : 0) + lrow * GSTR + lhalf * 16) * 4);
        uint32_t db = sbase + (uint32_t)(((2 * G_TILE + (buf ? G_TILE : 0)) + lrow * GSTR + lhalf * 16) * 4);
        #pragma unroll
        for (int c = 0; c < 4; c++) cpasync16(da + c * 16, ax + c * 4);
        #pragma unroll
        for (int c = 0; c < 4; c++) cpasync16(db + c * 16, bx + c * 4);
        asm volatile("cp.async.commit_group;" ::: "memory");
    };

    float acc[4][4][4];
    #pragma unroll
    for (int i = 0; i < 4; i++)
        #pragma unroll
        for (int j = 0; j < 4; j++)
            #pragma unroll
            for (int r = 0; r < 4; r++) acc[i][j][r] = 0.0f;

    load_stage(0, 0);
    load_stage(1, 1);

    for (int s = 0; s < DIM_ / 32; s++) {
        const int buf = s & 1;
        if (s < DIM_ / 32 - 1) asm volatile("cp.async.wait_group 1;" ::: "memory");
        else                   asm volatile("cp.async.wait_group 0;" ::: "memory");
        __syncthreads();

        const float* A   = As[buf];
        const float* Bsm = Bs[buf];
        #pragma unroll
        for (int ks = 0; ks < 4; ks++) {
            const int kk = ks * 8 + t;
            uint32_t af[4][4];
            #pragma unroll
            for (int mt = 0; mt < 4; mt++) {
                const int r = warpM + mt * 16 + g;
                af[mt][0] = tf32u(A[r * GSTR + kk]);
                af[mt][1] = tf32u(A[(r + 8) * GSTR + kk]);
                af[mt][2] = tf32u(A[r * GSTR + kk + 4]);
                af[mt][3] = tf32u(A[(r + 8) * GSTR + kk + 4]);
            }
            #pragma unroll
            for (int nt = 0; nt < 4; nt++) {
                const int n = warpN + nt * 8 + g;
                uint32_t b0 = tf32u(Bsm[n * GSTR + kk]);
                uint32_t b1 = tf32u(Bsm[n * GSTR + kk + 4]);
                #pragma unroll
                for (int mt = 0; mt < 4; mt++)
                    mma8(acc[mt][nt], af[mt][0], af[mt][1], af[mt][2], af[mt][3], b0, b1);
            }
        }
        __syncthreads();
        if (s + 2 < DIM_ / 32) load_stage(buf, s + 2);
    }

    // epilogue: bias + scale + tf32 round + scatter
    #pragma unroll
    for (int nt = 0; nt < 4; nt++) {
        const int c0   = eBase + warpN + nt * 8 + 2 * t;
        const int tsel = c0 >> 10;
        const int rem  = c0 & (DIM_ - 1);
        const int h    = rem >> 6;
        const int hd   = rem & (HD_ - 1);
        float* dst = (tsel == 0) ? g_q : ((tsel == 1) ? g_k : g_v);
        const float sc = (tsel == 0) ? SCALE_ : 1.0f;
        const float bb0 = __ldg(bias + c0);
        const float bb1 = __ldg(bias + c0 + 1);
        #pragma unroll
        for (int mt = 0; mt < 4; mt++) {
            const int r0 = mBase + warpM + mt * 16 + g;
            #pragma unroll
            for (int half = 0; half < 2; half++) {
                const int row = r0 + half * 8;
                const int bi  = row >> 11;
                const int n   = row & (N_ - 1);
                float2 v;
                v.x = tf32r((acc[mt][nt][half * 2 + 0] + bb0) * sc);
                v.y = tf32r((acc[mt][nt][half * 2 + 1] + bb1) * sc);
                *(float2*)(dst + ((((size_t)bi * H_ + h) * N_ + n) * HD_ + hd)) = v;
            }
        }
    }
}

// ---------------------------------------------------------------------------
// Kernel 2: flash attention, mma.sync tf32.
// grid (N/128, B*H), 128 thr, 4 warps x 32 q-rows. Key tile 64.
// smem: Qs[128][68], Ks[64][68], Vs[64][72], Ps[128][68]  (105 KB)
// ---------------------------------------------------------------------------
#define QSTR 68
#define KSTR 68
#define VSTR 72
#define PSTR 68
#define OFF_K (128 * QSTR)
#define OFF_V (OFF_K + 64 * KSTR)
#define OFF_P (OFF_V + 64 * VSTR)
#define ATT_SMEM ((OFF_P + 128 * PSTR) * 4)

__global__ __launch_bounds__(128) void attn_kernel4(float* __restrict__ out)
{
    extern __shared__ float sm[];
    float* Qs = sm;
    float* Ks = sm + OFF_K;
    float* Vs = sm + OFF_V;
    float* Ps = sm + OFF_P;

    const int tid  = threadIdx.x;
    const int wid  = tid >> 5;
    const int lane = tid & 31;
    const int g    = lane >> 2;
    const int t    = lane & 3;
    const int warpQ = wid * 32;

    const int bh = blockIdx.y;
    const int bi = bh >> 4;
    const int h  = bh & 15;
    const int q0 = blockIdx.x * 128;

    const float* Qg = g_q + (size_t)bh * N_ * HD_ + (size_t)q0 * HD_;
    const float* Kg = g_k + (size_t)bh * N_ * HD_;
    const float* Vg = g_v + (size_t)bh * N_ * HD_;

    // load Q 128x64
    #pragma unroll
    for (int s = 0; s < 16; s++) {
        int slot = tid + s * 128;
        int row = slot >> 4;
        int c4  = (slot & 15) << 2;
        *(float4*)(Qs + row * QSTR + c4) = *(const float4*)(Qg + row * HD_ + c4);
    }

    float o[2][8][4];
    float mrow[2][2], lrow[2][2];
    #pragma unroll
    for (int mt = 0; mt < 2; mt++) {
        mrow[mt][0] = -1e30f; mrow[mt][1] = -1e30f;
        lrow[mt][0] = 0.0f;   lrow[mt][1] = 0.0f;
        #pragma unroll
        for (int nt = 0; nt < 8; nt++)
            #pragma unroll
            for (int r = 0; r < 4; r++) o[mt][nt][r] = 0.0f;
    }

    for (int kt = 0; kt < N_ / 64; kt++) {
        __syncthreads();
        #pragma unroll
        for (int s = 0; s < 8; s++) {
            int slot = tid + s * 128;
            int row = slot >> 4;
            int c4  = (slot & 15) << 2;
            *(float4*)(Ks + row * KSTR + c4) =
                *(const float4*)(Kg + (size_t)(kt * 64 + row) * HD_ + c4);
            *(float4*)(Vs + row * VSTR + c4) =
                *(const float4*)(Vg + (size_t)(kt * 64 + row) * HD_ + c4);
        }
        __syncthreads();

        // stage 1: S = Q K^T  (warp: 32q x 64k)
        float s_[2][8][4];
        #pragma unroll
        for (int mt = 0; mt < 2; mt++)
            #pragma unroll
            for (int nt = 0; nt < 8; nt++)
                #pragma unroll
                for (int r = 0; r < 4; r++) s_[mt][nt][r] = 0.0f;

        #pragma unroll
        for (int ks = 0; ks < 8; ks++) {
            const int kk = ks * 8 + t;
            uint32_t af[2][4];
            #pragma unroll
            for (int mt = 0; mt < 2; mt++) {
                const int r = warpQ + mt * 16 + g;
                af[mt][0] = f2u(Qs[r * QSTR + kk]);
                af[mt][1] = f2u(Qs[(r + 8) * QSTR + kk]);
                af[mt][2] = f2u(Qs[r * QSTR + kk + 4]);
                af[mt][3] = f2u(Qs[(r + 8) * QSTR + kk + 4]);
            }
            #pragma unroll
            for (int nt = 0; nt < 8; nt++) {
                const int n = nt * 8 + g;
                uint32_t b0 = f2u(Ks[n * KSTR + kk]);
                uint32_t b1 = f2u(Ks[n * KSTR + kk + 4]);
                #pragma unroll
                for (int mt = 0; mt < 2; mt++)
                    mma8(s_[mt][nt], af[mt][0], af[mt][1], af[mt][2], af[mt][3], b0, b1);
            }
        }

        // online softmax per mt: rows g (regs 0,1) and g+8 (regs 2,3)
        #pragma unroll
        for (int mt = 0; mt < 2; mt++) {
            float mx0 = -1e30f, mx1 = -1e30f;
            #pragma unroll
            for (int nt = 0; nt < 8; nt++) {
                mx0 = fmaxf(mx0, fmaxf(s_[mt][nt][0], s_[mt][nt][1]));
                mx1 = fmaxf(mx1, fmaxf(s_[mt][nt][2], s_[mt][nt][3]));
            }
            mx0 = fmaxf(mx0, __shfl_xor_sync(0xffffffffu, mx0, 1));
            mx0 = fmaxf(mx0, __shfl_xor_sync(0xffffffffu, mx0, 2));
            mx1 = fmaxf(mx1, __shfl_xor_sync(0xffffffffu, mx1, 1));
            mx1 = fmaxf(mx1, __shfl_xor_sync(0xffffffffu, mx1, 2));
            const float nm0 = fmaxf(mrow[mt][0], mx0);
            const float nm1 = fmaxf(mrow[mt][1], mx1);
            const float corr0 = __expf(mrow[mt][0] - nm0);
            const float corr1 = __expf(mrow[mt][1] - nm1);
            mrow[mt][0] = nm0; mrow[mt][1] = nm1;

            float rs0 = 0.0f, rs1 = 0.0f;
            #pragma unroll
            for (int nt = 0; nt < 8; nt++) {
                float p0 = tf32r(__expf(s_[mt][nt][0] - nm0));
                float p1 = tf32r(__expf(s_[mt][nt][1] - nm0));
                float p2 = tf32r(__expf(s_[mt][nt][2] - nm1));
                float p3 = tf32r(__expf(s_[mt][nt][3] - nm1));
                rs0 += p0 + p1;
                rs1 += p2 + p3;
                const int c = nt * 8 + 2 * t;
                const int r = warpQ + mt * 16 + g;
                *(float2*)(Ps + r * PSTR + c)       = make_float2(p0, p1);
                *(float2*)(Ps + (r + 8) * PSTR + c) = make_float2(p2, p3);
            }
            rs0 += __shfl_xor_sync(0xffffffffu, rs0, 1);
            rs0 += __shfl_xor_sync(0xffffffffu, rs0, 2);
            rs1 += __shfl_xor_sync(0xffffffffu, rs1, 1);
            rs1 += __shfl_xor_sync(0xffffffffu, rs1, 2);
            lrow[mt][0] = lrow[mt][0] * corr0 + rs0;
            lrow[mt][1] = lrow[mt][1] * corr1 + rs1;

            #pragma unroll
            for (int nt = 0; nt < 8; nt++) {
                o[mt][nt][0] *= corr0; o[mt][nt][1] *= corr0;
                o[mt][nt][2] *= corr1; o[mt][nt][3] *= corr1;
            }
        }
        __syncwarp();   // Ps rows are warp-private

        // stage 2: O += P V  (warp: 32q x 64d over 64 keys)
        #pragma unroll
        for (int ks = 0; ks < 8; ks++) {
            const int kk = ks * 8 + t;
            uint32_t af[2][4];
            #pragma unroll
            for (int mt = 0; mt < 2; mt++) {
                const int r = warpQ + mt * 16 + g;
                af[mt][0] = f2u(Ps[r * PSTR + kk]);
                af[mt][1] = f2u(Ps[(r + 8) * PSTR + kk]);
                af[mt][2] = f2u(Ps[r * PSTR + kk + 4]);
                af[mt][3] = f2u(Ps[(r + 8) * PSTR + kk + 4]);
            }
            #pragma unroll
            for (int nt = 0; nt < 8; nt++) {
                const int n = nt * 8 + g;
                uint32_t b0 = f2u(Vs[(ks * 8 + t) * VSTR + n]);
                uint32_t b1 = f2u(Vs[(ks * 8 + t + 4) * VSTR + n]);
                #pragma unroll
                for (int mt = 0; mt < 2; mt++)
                    mma8(o[mt][nt], af[mt][0], af[mt][1], af[mt][2], af[mt][3], b0, b1);
            }
        }
    }

    // normalize + store
    #pragma unroll
    for (int mt = 0; mt < 2; mt++) {
        const float inv0 = 1.0f / lrow[mt][0];
        const float inv1 = 1.0f / lrow[mt][1];
        const int n0 = q0 + warpQ + mt * 16 + g;
        float* po0 = out + ((size_t)bi * N_ + n0) * DIM_ + h * HD_;
        float* po1 = out + ((size_t)bi * N_ + n0 + 8) * DIM_ + h * HD_;
        #pragma unroll
        for (int nt = 0; nt < 8; nt++) {
            const int c = nt * 8 + 2 * t;
            *(float2*)(po0 + c) = make_float2(o[mt][nt][0] * inv0, o[mt][nt][1] * inv0);
            *(float2*)(po1 + c) = make_float2(o[mt][nt][2] * inv1, o[mt][nt][3] * inv1);
        }
    }
}

// ---------------------------------------------------------------------------
extern "C" void kernel_launch(void* const* d_in, const int* in_sizes, int n_in,
                              void* d_out, int out_size)
{
    const float* x    = (const float*)d_in[0];
    const float* wqkv = (const float*)d_in[1];
    const float* bqkv = (const float*)d_in[2];
    float* out = (float*)d_out;

    cudaFuncSetAttribute(qkv_mma_kernel,
                         cudaFuncAttributeMaxDynamicSharedMemorySize, G_SMEM_BYTES);
    cudaFuncSetAttribute(attn_kernel4,
                         cudaFuncAttributeMaxDynamicSharedMemorySize, ATT_SMEM);

    dim3 ggrid(E3_ / 128, M_ / 128);   // (24, 64)
    qkv_mma_kernel<<<ggrid, 256, G_SMEM_BYTES>>>(x, wqkv, bqkv);

    dim3 agrid(N_ / 128, B_ * H_);     // (16, 64)
    attn_kernel4<<<agrid, 128, ATT_SMEM>>>(out);
}

// round 8
// speedup vs baseline: 1.0968x; 1.0968x over previous
#include <cuda_runtime.h>
#include <cstdint>

#define B_   4
#define N_   2048
#define DIM_ 1024
#define H_   16
#define HD_  64
#define E3_  3072
#define M_   8192
#define SCALE_ 0.125f

__device__ float g_q[(size_t)B_ * H_ * N_ * HD_];
__device__ float g_k[(size_t)B_ * H_ * N_ * HD_];
__device__ float g_v[(size_t)B_ * H_ * N_ * HD_];

// ---------------------------------------------------------------------------
// helpers
// ---------------------------------------------------------------------------
__device__ __forceinline__ float tf32r(float x) {
    uint32_t u;
    asm("cvt.rna.tf32.f32 %0, %1;" : "=r"(u) : "f"(x));
    return __uint_as_float(u);
}
__device__ __forceinline__ uint32_t tf32u(float x) {
    uint32_t u;
    asm("cvt.rna.tf32.f32 %0, %1;" : "=r"(u) : "f"(x));
    return u;
}
__device__ __forceinline__ uint32_t smem_u32(const void* p) {
    uint32_t a;
    asm("{ .reg .u64 t; cvta.to.shared.u64 t, %1; cvt.u32.u64 %0, t; }"
        : "=r"(a) : "l"(p));
    return a;
}
__device__ __forceinline__ void cpasync16(uint32_t dst, const void* src) {
    asm volatile("cp.async.cg.shared.global [%0], [%1], 16;"
                 :: "r"(dst), "l"(src) : "memory");
}
__device__ __forceinline__ void mma8(float* d,
                                     uint32_t a0, uint32_t a1, uint32_t a2, uint32_t a3,
                                     uint32_t b0, uint32_t b1) {
    asm volatile(
        "mma.sync.aligned.m16n8k8.row.col.f32.tf32.tf32.f32 "
        "{%0,%1,%2,%3}, {%4,%5,%6,%7}, {%8,%9}, {%0,%1,%2,%3};"
        : "+f"(d[0]), "+f"(d[1]), "+f"(d[2]), "+f"(d[3])
        : "r"(a0), "r"(a1), "r"(a2), "r"(a3), "r"(b0), "r"(b1));
}
__device__ __forceinline__ uint32_t f2u(float x) { return __float_as_uint(x); }

// ---------------------------------------------------------------------------
// Kernel 1: QKV projection, mma.sync tf32, fused cvt.rna rounding.
// CTA tile 256(m) x 128(e), BK=32 double-buffered, 512 thr, 16 warps (4m x 4e),
// warp tile 64x32 (64 accum regs/thread -- proven-safe shape).
// L2 traffic: 768 CTAs x 1.5MB = 1.15 GB (was 1.5 GB).
// ---------------------------------------------------------------------------
#define GSTR 36
#define A_TILE (256 * GSTR)      // 9216 floats
#define B_TILE (128 * GSTR)      // 4608 floats
#define OFF_A1 A_TILE
#define OFF_B0 (2 * A_TILE)
#define OFF_B1 (2 * A_TILE + B_TILE)
#define G_SMEM_BYTES ((2 * A_TILE + 2 * B_TILE) * 4)   // 110592 B

__global__ __launch_bounds__(512) void qkv_mma_kernel(
    const float* __restrict__ X, const float* __restrict__ W,
    const float* __restrict__ bias)
{
    extern __shared__ float smg[];
    const uint32_t sbase = smem_u32(smg);

    const int tid  = threadIdx.x;
    const int wid  = tid >> 5;
    const int lane = tid & 31;
    const int g    = lane >> 2;
    const int t    = lane & 3;
    const int warpM = (wid >> 2) * 64;   // 0,64,128,192
    const int warpN = (wid & 3) * 32;    // 0,32,64,96
    const int mBase = blockIdx.y * 256;
    const int eBase = blockIdx.x * 128;

    // A loader: row = tid>>1 (0..255), half = tid&1 -> 16 floats (4 cp16)
    const int arow  = tid >> 1;
    const int ahalf = tid & 1;
    // B loader: row = tid>>2 (0..127), quarter = tid&3 -> 8 floats (2 cp16)
    const int brow  = tid >> 2;
    const int bq    = tid & 3;

    auto load_stage = [&](int buf, int s) {
        const int k0 = s * 32;
        const float* ax = X + (size_t)(mBase + arow) * DIM_ + k0 + ahalf * 16;
        const float* bx = W + (size_t)(eBase + brow) * DIM_ + k0 + bq * 8;
        uint32_t da = sbase + (uint32_t)(((buf ? OFF_A1 : 0) + arow * GSTR + ahalf * 16) * 4);
        uint32_t db = sbase + (uint32_t)(((buf ? OFF_B1 : OFF_B0) + brow * GSTR + bq * 8) * 4);
        #pragma unroll
        for (int c = 0; c < 4; c++) cpasync16(da + c * 16, ax + c * 4);
        #pragma unroll
        for (int c = 0; c < 2; c++) cpasync16(db + c * 16, bx + c * 4);
        asm volatile("cp.async.commit_group;" ::: "memory");
    };

    float acc[4][4][4];
    #pragma unroll
    for (int i = 0; i < 4; i++)
        #pragma unroll
        for (int j = 0; j < 4; j++)
            #pragma unroll
            for (int r = 0; r < 4; r++) acc[i][j][r] = 0.0f;

    load_stage(0, 0);
    load_stage(1, 1);

    for (int s = 0; s < DIM_ / 32; s++) {
        const int buf = s & 1;
        if (s < DIM_ / 32 - 1) asm volatile("cp.async.wait_group 1;" ::: "memory");
        else                   asm volatile("cp.async.wait_group 0;" ::: "memory");
        __syncthreads();

        const float* A   = smg + (buf ? OFF_A1 : 0);
        const float* Bsm = smg + (buf ? OFF_B1 : OFF_B0);
        #pragma unroll
        for (int ks = 0; ks < 4; ks++) {
            const int kk = ks * 8 + t;
            uint32_t af[4][4];
            #pragma unroll
            for (int mt = 0; mt < 4; mt++) {
                const int r = warpM + mt * 16 + g;
                af[mt][0] = tf32u(A[r * GSTR + kk]);
                af[mt][1] = tf32u(A[(r + 8) * GSTR + kk]);
                af[mt][2] = tf32u(A[r * GSTR + kk + 4]);
                af[mt][3] = tf32u(A[(r + 8) * GSTR + kk + 4]);
            }
            #pragma unroll
            for (int nt = 0; nt < 4; nt++) {
                const int n = warpN + nt * 8 + g;
                uint32_t b0 = tf32u(Bsm[n * GSTR + kk]);
                uint32_t b1 = tf32u(Bsm[n * GSTR + kk + 4]);
                #pragma unroll
                for (int mt = 0; mt < 4; mt++)
                    mma8(acc[mt][nt], af[mt][0], af[mt][1], af[mt][2], af[mt][3], b0, b1);
            }
        }
        __syncthreads();
        if (s + 2 < DIM_ / 32) load_stage(buf, s + 2);
    }

    // epilogue: bias + scale + tf32 round + scatter
    #pragma unroll
    for (int nt = 0; nt < 4; nt++) {
        const int c0   = eBase + warpN + nt * 8 + 2 * t;
        const int tsel = c0 >> 10;
        const int rem  = c0 & (DIM_ - 1);
        const int h    = rem >> 6;
        const int hd   = rem & (HD_ - 1);
        float* dst = (tsel == 0) ? g_q : ((tsel == 1) ? g_k : g_v);
        const float sc = (tsel == 0) ? SCALE_ : 1.0f;
        const float bb0 = __ldg(bias + c0);
        const float bb1 = __ldg(bias + c0 + 1);
        #pragma unroll
        for (int mt = 0; mt < 4; mt++) {
            const int r0 = mBase + warpM + mt * 16 + g;
            #pragma unroll
            for (int half = 0; half < 2; half++) {
                const int row = r0 + half * 8;
                const int bi  = row >> 11;
                const int n   = row & (N_ - 1);
                float2 v;
                v.x = tf32r((acc[mt][nt][half * 2 + 0] + bb0) * sc);
                v.y = tf32r((acc[mt][nt][half * 2 + 1] + bb1) * sc);
                *(float2*)(dst + ((((size_t)bi * H_ + h) * N_ + n) * HD_ + hd)) = v;
            }
        }
    }
}

// ---------------------------------------------------------------------------
// Kernel 2: flash attention, mma.sync tf32, register shfl-transpose of P
// (no Ps smem). grid (N/128, B*H), 128 thr, 4 warps x 32 q-rows, key tile 64.
// smem: Qs[128][68] + Ks[64][68] + Vs[64][72] = 70656 B -> 3 CTAs/SM.
// ---------------------------------------------------------------------------
#define QSTR 68
#define KSTR 68
#define VSTR 72
#define AOFF_K (128 * QSTR)
#define AOFF_V (AOFF_K + 64 * KSTR)
#define ATT_SMEM ((AOFF_V + 64 * VSTR) * 4)

__global__ __launch_bounds__(128, 3) void attn_kernel5(float* __restrict__ out)
{
    extern __shared__ float sm[];
    float* Qs = sm;
    float* Ks = sm + AOFF_K;
    float* Vs = sm + AOFF_V;
    const uint32_t sbase = smem_u32(sm);

    const int tid  = threadIdx.x;
    const int wid  = tid >> 5;
    const int lane = tid & 31;
    const int g    = lane >> 2;
    const int t    = lane & 3;
    const int warpQ = wid * 32;
    const int odd  = lane & 1;
    const int src0 = (lane & ~3) | ((lane & 3) >> 1);
    const int src1 = src0 + 2;

    const int bh = blockIdx.y;
    const int bi = bh >> 4;
    const int h  = bh & 15;
    const int q0 = blockIdx.x * 128;

    const float* Qg = g_q + (size_t)bh * N_ * HD_ + (size_t)q0 * HD_;
    const float* Kg = g_k + (size_t)bh * N_ * HD_;
    const float* Vg = g_v + (size_t)bh * N_ * HD_;

    // load Q 128x64
    #pragma unroll
    for (int s = 0; s < 16; s++) {
        int slot = tid + s * 128;
        int row = slot >> 4;
        int c4  = (slot & 15) << 2;
        *(float4*)(Qs + row * QSTR + c4) = *(const float4*)(Qg + row * HD_ + c4);
    }

    float o[2][8][4];
    float mrow[2][2], lrow[2][2];
    #pragma unroll
    for (int mt = 0; mt < 2; mt++) {
        mrow[mt][0] = -1e30f; mrow[mt][1] = -1e30f;
        lrow[mt][0] = 0.0f;   lrow[mt][1] = 0.0f;
        #pragma unroll
        for (int nt = 0; nt < 8; nt++)
            #pragma unroll
            for (int r = 0; r < 4; r++) o[mt][nt][r] = 0.0f;
    }

    for (int kt = 0; kt < N_ / 64; kt++) {
        __syncthreads();           // everyone done reading prev K/V
        // cp.async K and V 64x64 tiles
        #pragma unroll
        for (int s = 0; s < 4; s++) {
            int slot = tid + s * 128;
            int row = slot >> 3;          // 0..63
            int c4  = (slot & 7) << 3;    // 0,8,..,56
            const float* kp = Kg + (size_t)(kt * 64 + row) * HD_ + c4;
            const float* vp = Vg + (size_t)(kt * 64 + row) * HD_ + c4;
            uint32_t dk = sbase + (uint32_t)((AOFF_K + row * KSTR + c4) * 4);
            uint32_t dv = sbase + (uint32_t)((AOFF_V + row * VSTR + c4) * 4);
            cpasync16(dk,      kp);
            cpasync16(dk + 16, kp + 4);
            cpasync16(dv,      vp);
            cpasync16(dv + 16, vp + 4);
        }
        asm volatile("cp.async.commit_group;" ::: "memory");
        asm volatile("cp.async.wait_group 0;" ::: "memory");
        __syncthreads();

        // stage 1: S = Q K^T  (warp: 32q x 64k)
        float s_[2][8][4];
        #pragma unroll
        for (int mt = 0; mt < 2; mt++)
            #pragma unroll
            for (int nt = 0; nt < 8; nt++)
                #pragma unroll
                for (int r = 0; r < 4; r++) s_[mt][nt][r] = 0.0f;

        #pragma unroll
        for (int ks = 0; ks < 8; ks++) {
            const int kk = ks * 8 + t;
            uint32_t af[2][4];
            #pragma unroll
            for (int mt = 0; mt < 2; mt++) {
                const int r = warpQ + mt * 16 + g;
                af[mt][0] = f2u(Qs[r * QSTR + kk]);
                af[mt][1] = f2u(Qs[(r + 8) * QSTR + kk]);
                af[mt][2] = f2u(Qs[r * QSTR + kk + 4]);
                af[mt][3] = f2u(Qs[(r + 8) * QSTR + kk + 4]);
            }
            #pragma unroll
            for (int nt = 0; nt < 8; nt++) {
                const int n = nt * 8 + g;
                uint32_t b0 = f2u(Ks[n * KSTR + kk]);
                uint32_t b1 = f2u(Ks[n * KSTR + kk + 4]);
                #pragma unroll
                for (int mt = 0; mt < 2; mt++)
                    mma8(s_[mt][nt], af[mt][0], af[mt][1], af[mt][2], af[mt][3], b0, b1);
            }
        }

        // online softmax; rounded P kept in s_ (registers)
        #pragma unroll
        for (int mt = 0; mt < 2; mt++) {
            float mx0 = -1e30f, mx1 = -1e30f;
            #pragma unroll
            for (int nt = 0; nt < 8; nt++) {
                mx0 = fmaxf(mx0, fmaxf(s_[mt][nt][0], s_[mt][nt][1]));
                mx1 = fmaxf(mx1, fmaxf(s_[mt][nt][2], s_[mt][nt][3]));
            }
            mx0 = fmaxf(mx0, __shfl_xor_sync(0xffffffffu, mx0, 1));
            mx0 = fmaxf(mx0, __shfl_xor_sync(0xffffffffu, mx0, 2));
            mx1 = fmaxf(mx1, __shfl_xor_sync(0xffffffffu, mx1, 1));
            mx1 = fmaxf(mx1, __shfl_xor_sync(0xffffffffu, mx1, 2));
            const float nm0 = fmaxf(mrow[mt][0], mx0);
            const float nm1 = fmaxf(mrow[mt][1], mx1);
            const float corr0 = __expf(mrow[mt][0] - nm0);
            const float corr1 = __expf(mrow[mt][1] - nm1);
            mrow[mt][0] = nm0; mrow[mt][1] = nm1;

            float rs0 = 0.0f, rs1 = 0.0f;
            #pragma unroll
            for (int nt = 0; nt < 8; nt++) {
                float p0 = tf32r(__expf(s_[mt][nt][0] - nm0));
                float p1 = tf32r(__expf(s_[mt][nt][1] - nm0));
                float p2 = tf32r(__expf(s_[mt][nt][2] - nm1));
                float p3 = tf32r(__expf(s_[mt][nt][3] - nm1));
                rs0 += p0 + p1;  rs1 += p2 + p3;
                s_[mt][nt][0] = p0; s_[mt][nt][1] = p1;
                s_[mt][nt][2] = p2; s_[mt][nt][3] = p3;
            }
            rs0 += __shfl_xor_sync(0xffffffffu, rs0, 1);
            rs0 += __shfl_xor_sync(0xffffffffu, rs0, 2);
            rs1 += __shfl_xor_sync(0xffffffffu, rs1, 1);
            rs1 += __shfl_xor_sync(0xffffffffu, rs1, 2);
            lrow[mt][0] = lrow[mt][0] * corr0 + rs0;
            lrow[mt][1] = lrow[mt][1] * corr1 + rs1;

            #pragma unroll
            for (int nt = 0; nt < 8; nt++) {
                o[mt][nt][0] *= corr0; o[mt][nt][1] *= corr0;
                o[mt][nt][2] *= corr1; o[mt][nt][3] *= corr1;
            }
        }

        // stage 2: O += P V ; P a-frags built from s_ via shfl transpose.
        // a-frag col c of tile ks lives in quad-lane (c>>1), reg parity (c&1).
        #pragma unroll
        for (int ks = 0; ks < 8; ks++) {
            uint32_t af[2][4];
            #pragma unroll
            for (int mt = 0; mt < 2; mt++) {
                float x0 = __shfl_sync(0xffffffffu, s_[mt][ks][0], src0);
                float x1 = __shfl_sync(0xffffffffu, s_[mt][ks][1], src0);
                float x2 = __shfl_sync(0xffffffffu, s_[mt][ks][2], src0);
                float x3 = __shfl_sync(0xffffffffu, s_[mt][ks][3], src0);
                float y0 = __shfl_sync(0xffffffffu, s_[mt][ks][0], src1);
                float y1 = __shfl_sync(0xffffffffu, s_[mt][ks][1], src1);
                float y2 = __shfl_sync(0xffffffffu, s_[mt][ks][2], src1);
                float y3 = __shfl_sync(0xffffffffu, s_[mt][ks][3], src1);
                af[mt][0] = f2u(odd ? x1 : x0);
                af[mt][1] = f2u(odd ? x3 : x2);
                af[mt][2] = f2u(odd ? y1 : y0);
                af[mt][3] = f2u(odd ? y3 : y2);
            }
            #pragma unroll
            for (int nt = 0; nt < 8; nt++) {
                const int n = nt * 8 + g;
                uint32_t b0 = f2u(Vs[(ks * 8 + t) * VSTR + n]);
                uint32_t b1 = f2u(Vs[(ks * 8 + t + 4) * VSTR + n]);
                #pragma unroll
                for (int mt = 0; mt < 2; mt++)
                    mma8(o[mt][nt], af[mt][0], af[mt][1], af[mt][2], af[mt][3], b0, b1);
            }
        }
    }

    // normalize + store
    #pragma unroll
    for (int mt = 0; mt < 2; mt++) {
        const float inv0 = 1.0f / lrow[mt][0];
        const float inv1 = 1.0f / lrow[mt][1];
        const int n0 = q0 + warpQ + mt * 16 + g;
        float* po0 = out + ((size_t)bi * N_ + n0) * DIM_ + h * HD_;
        float* po1 = out + ((size_t)bi * N_ + n0 + 8) * DIM_ + h * HD_;
        #pragma unroll
        for (int nt = 0; nt < 8; nt++) {
            const int c = nt * 8 + 2 * t;
            *(float2*)(po0 + c) = make_float2(o[mt][nt][0] * inv0, o[mt][nt][1] * inv0);
            *(float2*)(po1 + c) = make_float2(o[mt][nt][2] * inv1, o[mt][nt][3] * inv1);
        }
    }
}

// ---------------------------------------------------------------------------
extern "C" void kernel_launch(void* const* d_in, const int* in_sizes, int n_in,
                              void* d_out, int out_size)
{
    const float* x    = (const float*)d_in[0];
    const float* wqkv = (const float*)d_in[1];
    const float* bqkv = (const float*)d_in[2];
    float* out = (float*)d_out;

    cudaFuncSetAttribute(qkv_mma_kernel,
                         cudaFuncAttributeMaxDynamicSharedMemorySize, G_SMEM_BYTES);
    cudaFuncSetAttribute(attn_kernel5,
                         cudaFuncAttributeMaxDynamicSharedMemorySize, ATT_SMEM);

    dim3 ggrid(E3_ / 128, M_ / 256);   // (24, 32)
    qkv_mma_kernel<<<ggrid, 512, G_SMEM_BYTES>>>(x, wqkv, bqkv);

    dim3 agrid(N_ / 128, B_ * H_);     // (16, 64)
    attn_kernel5<<<agrid, 128, ATT_SMEM>>>(out);
}